// round 2
// baseline (speedup 1.0000x reference)
#include <cuda_runtime.h>
#include <cstddef>

// ---------------- scratch (static __device__ globals; no allocations) ----------------
__device__ float g_x1[(size_t)64 * 64 * 112 * 112];   // 205 MB
__device__ float g_x2[(size_t)64 * 128 * 56 * 56];    // 102 MB
__device__ float g_x3[(size_t)64 * 256 * 28 * 28];    // 51 MB
__device__ float g_x4[(size_t)64 * 512 * 14 * 14];    // 26 MB
__device__ float g_mean[64 * 512];
__device__ float g_sent[64 * 512];
__device__ float g_img[64 * 512];
__device__ float g_feats[64 * 1024];
__device__ float g_h1[64 * 512];
__device__ float g_h2[64 * 512];

// ---------------- embedding masked mean: mean[b,d] = sum_{s<len} emb[seq[b,s],d] / len ----------------
__global__ void embed_mean_k(const int* __restrict__ seq, const int* __restrict__ len,
                             const float* __restrict__ emb, float* __restrict__ mean) {
    const int b = blockIdx.x;
    const int L = len[b];
    __shared__ int s_idx[128];
    for (int i = threadIdx.x; i < 128; i += blockDim.x) s_idx[i] = seq[b * 128 + i];
    __syncthreads();
    const float inv = 1.0f / (float)L;
    for (int d = threadIdx.x; d < 512; d += blockDim.x) {
        float acc = 0.0f;
        for (int s = 0; s < L; s++) acc += emb[(size_t)s_idx[s] * 512 + d];
        mean[b * 512 + d] = acc * inv;
    }
}

// ---------------- generic small linear: Y[b,j] = act(sum_k X[b,k]*W[k,j] + bias[j]) ----------------
__global__ void linear_k(const float* __restrict__ X, const float* __restrict__ W,
                         const float* __restrict__ bias, float* __restrict__ Y,
                         int K, int N, int relu) {
    const int j = blockIdx.x * blockDim.x + threadIdx.x;
    const int b = blockIdx.y;
    if (j >= N) return;
    const float* x = X + (size_t)b * K;
    float acc = bias[j];
    for (int k = 0; k < K; k++) acc = fmaf(x[k], W[(size_t)k * N + j], acc);
    if (relu && acc < 0.0f) acc = 0.0f;
    Y[(size_t)b * N + j] = acc;
}

// ---------------- direct strided 3x3 conv, stride 2, SAME (pad bottom/right only) ----------------
// Block: 64 output channels x (8 rows x 16 cols) output tile, one image.
// Thread (cg=tid>>5, pg=tid&31): 8 channels x 4 consecutive output cols.
template <int CIN, int COUT, int HIN, int WIN>
__global__ void __launch_bounds__(256) conv_k(const float* __restrict__ in,
                                              const float* __restrict__ w,
                                              const float* __restrict__ bias,
                                              float* __restrict__ out) {
    constexpr int HOUT = HIN / 2, WOUT = WIN / 2;
    constexpr int TH = 8, TW = 16;
    constexpr int COUT_BLK = 64;
    constexpr int CC = (CIN < 8) ? CIN : 8;   // cin chunk (3 for conv1, 8 otherwise)
    constexpr int IH = 2 * TH + 1;            // 17
    constexpr int IW = 2 * TW + 1;            // 33 (odd -> conflict-free strided reads)

    // __align__(16): s_w is read with LDS.128 (float4); shared arrays are only
    // element-aligned by default and a misaligned LDS.128 traps.
    __shared__ __align__(16) float s_in[CC][IH][IW];
    __shared__ __align__(16) float s_w[CC][9][COUT_BLK];

    constexpr int TILESX = (WOUT + TW - 1) / TW;
    const int tile = blockIdx.x;
    const int ty0 = (tile / TILESX) * TH;
    const int tx0 = (tile % TILESX) * TW;
    const int cob = blockIdx.y * COUT_BLK;
    const int n = blockIdx.z;

    const int tid = threadIdx.x;
    const int cg = tid >> 5;          // 0..7 (uniform per warp -> weight loads broadcast)
    const int pg = tid & 31;          // 0..31
    const int lrow = pg >> 2;         // local output row 0..7
    const int lcol0 = (pg & 3) * 4;   // local output col base 0..12

    float acc[8][4];
#pragma unroll
    for (int i = 0; i < 8; i++)
#pragma unroll
        for (int j = 0; j < 4; j++) acc[i][j] = 0.0f;

    const int iy0 = 2 * ty0;
    const int ix0 = 2 * tx0;
    const float* in_n = in + (size_t)n * CIN * HIN * WIN;

    for (int c0 = 0; c0 < CIN; c0 += CC) {
        if (c0) __syncthreads();
        // load input tile (zero-fill OOB: SAME pads only bottom/right by 1)
        for (int idx = tid; idx < CC * IH * IW; idx += 256) {
            int c = idx / (IH * IW);
            int rem = idx - c * (IH * IW);
            int r = rem / IW;
            int x = rem - r * IW;
            int gy = iy0 + r, gx = ix0 + x;
            float v = 0.0f;
            if (gy < HIN && gx < WIN)
                v = in_n[(size_t)(c0 + c) * HIN * WIN + (size_t)gy * WIN + gx];
            s_in[c][r][x] = v;
        }
        // load weights chunk: OIHW -> s_w[cin][k][cout]
        for (int idx = tid; idx < CC * 9 * COUT_BLK; idx += 256) {
            int c = idx / (9 * COUT_BLK);
            int rem = idx - c * (9 * COUT_BLK);
            int k = rem / COUT_BLK;
            int co = rem - k * COUT_BLK;
            s_w[c][k][co] = w[((size_t)(cob + co) * CIN + (c0 + c)) * 9 + k];
        }
        __syncthreads();

        for (int c = 0; c < CC; c++) {
#pragma unroll
            for (int k = 0; k < 9; k++) {
                const int ky = k / 3, kx = k % 3;
                const float4 w0 = *(const float4*)&s_w[c][k][cg * 8];
                const float4 w1 = *(const float4*)&s_w[c][k][cg * 8 + 4];
                const float wv[8] = {w0.x, w0.y, w0.z, w0.w, w1.x, w1.y, w1.z, w1.w};
                const float* rowp = &s_in[c][2 * lrow + ky][2 * lcol0 + kx];
                float iv[4];
#pragma unroll
                for (int j = 0; j < 4; j++) iv[j] = rowp[2 * j];
#pragma unroll
                for (int i = 0; i < 8; i++)
#pragma unroll
                    for (int j = 0; j < 4; j++) acc[i][j] = fmaf(wv[i], iv[j], acc[i][j]);
            }
        }
    }

    const int orow = ty0 + lrow;
    if (orow < HOUT) {
        float* out_n = out + (size_t)n * COUT * HOUT * WOUT;
#pragma unroll
        for (int i = 0; i < 8; i++) {
            const int co = cob + cg * 8 + i;
            const float bv = bias[co];
            float* op = out_n + (size_t)co * HOUT * WOUT + (size_t)orow * WOUT;
#pragma unroll
            for (int j = 0; j < 4; j++) {
                int oc = tx0 + lcol0 + j;
                if (oc < WOUT) {
                    float v = acc[i][j] + bv;
                    op[oc] = v > 0.0f ? v : 0.0f;
                }
            }
        }
    }
}

// ---------------- global average pool over 14x14: one warp per (n,c) ----------------
__global__ void pool_k(const float* __restrict__ x, float* __restrict__ y) {
    const int idx = blockIdx.x * 8 + (threadIdx.x >> 5);   // nc index, 64*512 total
    const int lane = threadIdx.x & 31;
    const float* p = x + (size_t)idx * 196;
    float s = 0.0f;
    for (int i = lane; i < 196; i += 32) s += p[i];
#pragma unroll
    for (int o = 16; o; o >>= 1) s += __shfl_down_sync(0xFFFFFFFFu, s, o);
    if (lane == 0) y[idx] = s * (1.0f / 196.0f);
}

// ---------------- feats = concat(img, sent) ----------------
__global__ void concat_k(const float* __restrict__ img, const float* __restrict__ sent,
                         float* __restrict__ feats) {
    const int i = blockIdx.x * blockDim.x + threadIdx.x;   // 64*1024
    const int b = i >> 10, j = i & 1023;
    feats[i] = (j < 512) ? img[b * 512 + j] : sent[b * 512 + (j - 512)];
}

// ---------------- launch ----------------
extern "C" void kernel_launch(void* const* d_in, const int* in_sizes, int n_in,
                              void* d_out, int out_size) {
    const float* images = (const float*)d_in[0];
    const int*   seq    = (const int*)d_in[1];
    const int*   len    = (const int*)d_in[2];
    // d_in[3] = lengths_var (unused by reference math)
    const float* emb    = (const float*)d_in[4];
    const float* cw1    = (const float*)d_in[5];
    const float* cb1    = (const float*)d_in[6];
    const float* cw2    = (const float*)d_in[7];
    const float* cb2    = (const float*)d_in[8];
    const float* cw3    = (const float*)d_in[9];
    const float* cb3    = (const float*)d_in[10];
    const float* cw4    = (const float*)d_in[11];
    const float* cb4    = (const float*)d_in[12];
    const float* rnn_w  = (const float*)d_in[13];
    const float* rnn_b  = (const float*)d_in[14];
    const float* fc1_w  = (const float*)d_in[15];
    const float* fc1_b  = (const float*)d_in[16];
    const float* fc2_w  = (const float*)d_in[17];
    const float* fc2_b  = (const float*)d_in[18];
    const float* clf_w  = (const float*)d_in[19];
    const float* clf_b  = (const float*)d_in[20];
    float* out = (float*)d_out;

    float *x1, *x2, *x3, *x4, *mean, *sent, *img, *feats, *h1, *h2;
    cudaGetSymbolAddress((void**)&x1, g_x1);
    cudaGetSymbolAddress((void**)&x2, g_x2);
    cudaGetSymbolAddress((void**)&x3, g_x3);
    cudaGetSymbolAddress((void**)&x4, g_x4);
    cudaGetSymbolAddress((void**)&mean, g_mean);
    cudaGetSymbolAddress((void**)&sent, g_sent);
    cudaGetSymbolAddress((void**)&img, g_img);
    cudaGetSymbolAddress((void**)&feats, g_feats);
    cudaGetSymbolAddress((void**)&h1, g_h1);
    cudaGetSymbolAddress((void**)&h2, g_h2);

    // text branch
    embed_mean_k<<<64, 512>>>(seq, len, emb, mean);
    linear_k<<<dim3(2, 64), 256>>>(mean, rnn_w, rnn_b, sent, 512, 512, 0);

    // vision branch: conv grid.x = tilesx*tilesy, grid.y = COUT/64, grid.z = batch
    conv_k<3, 64, 224, 224><<<dim3(7 * 14, 1, 64), 256>>>(images, cw1, cb1, x1);
    conv_k<64, 128, 112, 112><<<dim3(4 * 7, 2, 64), 256>>>(x1, cw2, cb2, x2);
    conv_k<128, 256, 56, 56><<<dim3(2 * 4, 4, 64), 256>>>(x2, cw3, cb3, x3);
    conv_k<256, 512, 28, 28><<<dim3(1 * 2, 8, 64), 256>>>(x3, cw4, cb4, x4);
    pool_k<<<(64 * 512) / 8, 256>>>(x4, img);

    // head
    concat_k<<<(64 * 1024) / 256, 256>>>(img, sent, feats);
    linear_k<<<dim3(2, 64), 256>>>(feats, fc1_w, fc1_b, h1, 1024, 512, 1);
    linear_k<<<dim3(2, 64), 256>>>(h1, fc2_w, fc2_b, h2, 512, 512, 1);
    linear_k<<<dim3(4, 64), 256>>>(h2, clf_w, clf_b, out, 512, 1000, 0);
}